// round 3
// baseline (speedup 1.0000x reference)
#include <cuda_runtime.h>
#include <math.h>

#define DD 256      // D
#define EE 1024     // E
#define FF 1024     // F = 4*D
#define NROWS 4096  // N
#define F4 (FF / 4) // 256 float4 per f-row
#define DT 4        // d-rows per CTA in weff
#define FCH 64      // float4s of f per CTA in weff

// ---- static scratch (no allocations allowed) ----
__device__ float g_w[EE * EE];      // 4 MB: softmax gate weights
__device__ float g_Weff[DD * FF];   // 1 MB
__device__ float g_beff[FF];        // 4 KB

// ============================================================
// Kernel 1: gate GEMM  g_w[i,j] = x[i,:] @ gate_W[:,j] + gate_b[j]
// i in [0,1024). 64x64 tile, BK=16, 256 threads, 4x4/thread.  (R1 proven)
// ============================================================
__global__ void gate_gemm(const float* __restrict__ x,
                          const float* __restrict__ gW,
                          const float* __restrict__ gb) {
    __shared__ float As[16][68];
    __shared__ float Bs[16][64];
    const int tid = threadIdx.x;
    const int i0 = blockIdx.y * 64;
    const int j0 = blockIdx.x * 64;
    const int tx = tid & 15;
    const int ty = tid >> 4;

    float acc[4][4];
#pragma unroll
    for (int r = 0; r < 4; r++)
#pragma unroll
        for (int c = 0; c < 4; c++) acc[r][c] = 0.f;

    for (int k0 = 0; k0 < DD; k0 += 16) {
#pragma unroll
        for (int t = 0; t < 4; t++) {
            int m = tid + t * 256;
            int r = m >> 4, c = m & 15;
            As[c][r] = x[(size_t)(i0 + r) * DD + k0 + c];
        }
#pragma unroll
        for (int t = 0; t < 4; t++) {
            int m = tid + t * 256;
            int r = m >> 6, c = m & 63;
            Bs[r][c] = gW[(size_t)(k0 + r) * EE + j0 + c];
        }
        __syncthreads();
#pragma unroll
        for (int k = 0; k < 16; k++) {
            float a[4], b[4];
#pragma unroll
            for (int r = 0; r < 4; r++) a[r] = As[k][ty * 4 + r];
#pragma unroll
            for (int c = 0; c < 4; c++) b[c] = Bs[k][tx * 4 + c];
#pragma unroll
            for (int r = 0; r < 4; r++)
#pragma unroll
                for (int c = 0; c < 4; c++) acc[r][c] += a[r] * b[c];
        }
        __syncthreads();
    }

#pragma unroll
    for (int r = 0; r < 4; r++) {
        int gi = i0 + ty * 4 + r;
        int gj = j0 + tx * 4;
        float4 v;
        v.x = acc[r][0] + gb[gj + 0];
        v.y = acc[r][1] + gb[gj + 1];
        v.z = acc[r][2] + gb[gj + 2];
        v.w = acc[r][3] + gb[gj + 3];
        *(float4*)&g_w[(size_t)gi * EE + gj] = v;
    }
}

// ============================================================
// Kernel 2: row softmax in-place on g_w (1024 rows x 1024)
// ============================================================
__global__ void softmax_rows() {
    const int row = blockIdx.x;
    const int tid = threadIdx.x;
    const int lane = tid & 31;
    const int wid = tid >> 5;
    float4* p = ((float4*)g_w) + (size_t)row * F4;
    float4 v = p[tid];

    __shared__ float red[8];
    __shared__ float bc;

    float m = fmaxf(fmaxf(v.x, v.y), fmaxf(v.z, v.w));
#pragma unroll
    for (int o = 16; o > 0; o >>= 1) m = fmaxf(m, __shfl_xor_sync(0xffffffffu, m, o));
    if (lane == 0) red[wid] = m;
    __syncthreads();
    if (tid == 0) {
        float t = red[0];
#pragma unroll
        for (int i = 1; i < 8; i++) t = fmaxf(t, red[i]);
        bc = t;
    }
    __syncthreads();
    m = bc;
    __syncthreads();

    v.x = expf(v.x - m); v.y = expf(v.y - m);
    v.z = expf(v.z - m); v.w = expf(v.w - m);
    float s = v.x + v.y + v.z + v.w;
#pragma unroll
    for (int o = 16; o > 0; o >>= 1) s += __shfl_xor_sync(0xffffffffu, s, o);
    if (lane == 0) red[wid] = s;
    __syncthreads();
    if (tid == 0) {
        float t = 0.f;
#pragma unroll
        for (int i = 0; i < 8; i++) t += red[i];
        bc = t;
    }
    __syncthreads();
    float inv = 1.f / bc;
    v.x *= inv; v.y *= inv; v.z *= inv; v.w *= inv;
    p[tid] = v;
}

// ============================================================
// Kernel 3: W_eff full reduction over e — NO split-K, no partials.
// grid (DD/DT=64, FF/(FCH*4)=4), 256 threads.
// Thread: f4 = tid&63 (within f-chunk), dlane = tid>>6 (0..3), owns one
// (d, float4-of-f) output. e-loop unrolled x4 with independent chains.
// beff folded into blockIdx.x==0 CTAs (dlane==0 threads).
// ============================================================
__global__ void weff_full(const float* __restrict__ eW,
                          const float* __restrict__ eb) {
    const int tid = threadIdx.x;
    const int f4 = tid & 63;
    const int dlane = tid >> 6;
    const int d = blockIdx.x * DT + dlane;
    const int f4g = blockIdx.y * FCH + f4;           // global float4 index of f
    const bool doB = (blockIdx.x == 0) && (dlane == 0);

    float4 a0 = make_float4(0.f, 0.f, 0.f, 0.f);
    float4 a1 = a0, a2 = a0, a3 = a0;
    float4 b0 = a0, b1 = a0, b2 = a0, b3 = a0;

    const float4* wp = ((const float4*)g_w) + f4g;                        // + e*F4
    const float4* ep = ((const float4*)eW) + (size_t)d * F4 + f4g;        // + e*DD*F4
    const float4* bp = ((const float4*)eb) + f4g;                         // + e*F4

    for (int e = 0; e < EE; e += 4) {
        float4 w0 = wp[(size_t)(e + 0) * F4];
        float4 w1 = wp[(size_t)(e + 1) * F4];
        float4 w2 = wp[(size_t)(e + 2) * F4];
        float4 w3 = wp[(size_t)(e + 3) * F4];
        float4 v0 = __ldcs(ep + (size_t)(e + 0) * DD * F4);
        float4 v1 = __ldcs(ep + (size_t)(e + 1) * DD * F4);
        float4 v2 = __ldcs(ep + (size_t)(e + 2) * DD * F4);
        float4 v3 = __ldcs(ep + (size_t)(e + 3) * DD * F4);
        a0.x += w0.x * v0.x; a0.y += w0.y * v0.y; a0.z += w0.z * v0.z; a0.w += w0.w * v0.w;
        a1.x += w1.x * v1.x; a1.y += w1.y * v1.y; a1.z += w1.z * v1.z; a1.w += w1.w * v1.w;
        a2.x += w2.x * v2.x; a2.y += w2.y * v2.y; a2.z += w2.z * v2.z; a2.w += w2.w * v2.w;
        a3.x += w3.x * v3.x; a3.y += w3.y * v3.y; a3.z += w3.z * v3.z; a3.w += w3.w * v3.w;
        if (doB) {
            float4 e0 = __ldcs(bp + (size_t)(e + 0) * F4);
            float4 e1 = __ldcs(bp + (size_t)(e + 1) * F4);
            float4 e2 = __ldcs(bp + (size_t)(e + 2) * F4);
            float4 e3 = __ldcs(bp + (size_t)(e + 3) * F4);
            b0.x += w0.x * e0.x; b0.y += w0.y * e0.y; b0.z += w0.z * e0.z; b0.w += w0.w * e0.w;
            b1.x += w1.x * e1.x; b1.y += w1.y * e1.y; b1.z += w1.z * e1.z; b1.w += w1.w * e1.w;
            b2.x += w2.x * e2.x; b2.y += w2.y * e2.y; b2.z += w2.z * e2.z; b2.w += w2.w * e2.w;
            b3.x += w3.x * e3.x; b3.y += w3.y * e3.y; b3.z += w3.z * e3.z; b3.w += w3.w * e3.w;
        }
    }

    float4 s;
    s.x = (a0.x + a1.x) + (a2.x + a3.x);
    s.y = (a0.y + a1.y) + (a2.y + a3.y);
    s.z = (a0.z + a1.z) + (a2.z + a3.z);
    s.w = (a0.w + a1.w) + (a2.w + a3.w);
    ((float4*)g_Weff)[(size_t)d * F4 + f4g] = s;

    if (doB) {
        float4 t;
        t.x = (b0.x + b1.x) + (b2.x + b3.x);
        t.y = (b0.y + b1.y) + (b2.y + b3.y);
        t.z = (b0.z + b1.z) + (b2.z + b3.z);
        t.w = (b0.w + b1.w) + (b2.w + b3.w);
        ((float4*)g_beff)[f4g] = t;
    }
}

// ============================================================
// Kernel 4: final GEMM  out = x @ W_eff + b_eff
// M=4096, N=1024, K=256. 128x128 tile, BK=8, 256 thr, 8x8/thread. (R1 proven)
// ============================================================
__global__ void final_gemm(const float* __restrict__ x, float* __restrict__ out) {
    __shared__ float As[8][132];
    __shared__ float Bs[8][128];
    const int tid = threadIdx.x;
    const int i0 = blockIdx.y * 128;
    const int j0 = blockIdx.x * 128;
    const int tx = tid & 15;
    const int ty = tid >> 4;

    float acc[8][8];
#pragma unroll
    for (int r = 0; r < 8; r++)
#pragma unroll
        for (int c = 0; c < 8; c++) acc[r][c] = 0.f;

    for (int k0 = 0; k0 < DD; k0 += 8) {
        {
            int r = tid >> 1;
            int c = (tid & 1) * 4;
            float4 v = *(const float4*)&x[(size_t)(i0 + r) * DD + k0 + c];
            As[c + 0][r] = v.x;
            As[c + 1][r] = v.y;
            As[c + 2][r] = v.z;
            As[c + 3][r] = v.w;
        }
        {
            int r = tid >> 5;
            int c = (tid & 31) * 4;
            *(float4*)&Bs[r][c] = *(const float4*)&g_Weff[(size_t)(k0 + r) * FF + j0 + c];
        }
        __syncthreads();
#pragma unroll
        for (int k = 0; k < 8; k++) {
            float a[8], b[8];
            *(float4*)&a[0] = *(const float4*)&As[k][ty * 8];
            *(float4*)&a[4] = *(const float4*)&As[k][ty * 8 + 4];
            *(float4*)&b[0] = *(const float4*)&Bs[k][tx * 8];
            *(float4*)&b[4] = *(const float4*)&Bs[k][tx * 8 + 4];
#pragma unroll
            for (int r = 0; r < 8; r++)
#pragma unroll
                for (int c = 0; c < 8; c++) acc[r][c] += a[r] * b[c];
        }
        __syncthreads();
    }

    float bias[8];
#pragma unroll
    for (int c = 0; c < 8; c++) bias[c] = g_beff[j0 + tx * 8 + c];
#pragma unroll
    for (int r = 0; r < 8; r++) {
        int gi = i0 + ty * 8 + r;
        float4 v0, v1;
        v0.x = acc[r][0] + bias[0];
        v0.y = acc[r][1] + bias[1];
        v0.z = acc[r][2] + bias[2];
        v0.w = acc[r][3] + bias[3];
        v1.x = acc[r][4] + bias[4];
        v1.y = acc[r][5] + bias[5];
        v1.z = acc[r][6] + bias[6];
        v1.w = acc[r][7] + bias[7];
        *(float4*)&out[(size_t)gi * FF + j0 + tx * 8] = v0;
        *(float4*)&out[(size_t)gi * FF + j0 + tx * 8 + 4] = v1;
    }
}

// ============================================================
extern "C" void kernel_launch(void* const* d_in, const int* in_sizes, int n_in,
                              void* d_out, int out_size) {
    const float* x  = (const float*)d_in[0];   // (4096, 256)
    const float* gW = (const float*)d_in[1];   // (256, 1024)
    const float* gb = (const float*)d_in[2];   // (1024,)
    const float* eW = (const float*)d_in[3];   // (1024, 256, 1024)
    const float* eb = (const float*)d_in[4];   // (1024, 1024)
    float* out = (float*)d_out;                // (4096, 1024)

    gate_gemm<<<dim3(EE / 64, EE / 64), 256>>>(x, gW, gb);
    softmax_rows<<<EE, 256>>>();
    weff_full<<<dim3(DD / DT, FF / (FCH * 4)), 256>>>(eW, eb);
    final_gemm<<<dim3(FF / 128, NROWS / 128), 256>>>(x, out);
}

// round 4
// speedup vs baseline: 1.6460x; 1.6460x over previous
#include <cuda_runtime.h>
#include <math.h>

#define DD 256      // D
#define EE 1024     // E
#define FF 1024     // F = 4*D
#define NROWS 4096  // N
#define ESPLIT 32
#define ECHUNK (EE / ESPLIT)   // 32
#define DT 16

// ---- static scratch (no allocations allowed) ----
__device__ float g_w[EE * EE];                          // 4 MB: softmax gate weights
__device__ float g_part[(size_t)ESPLIT * DD * FF];      // 32 MB: split-K partials
__device__ float g_bpart[ESPLIT * FF];                  // 128 KB
__device__ float g_Weff[DD * FF];                       // 1 MB
__device__ float g_beff[FF];                            // 4 KB

// ============================================================
// Kernel 1: gate GEMM (R1-proven). 64x64 tile, 4x4/thread.
// ============================================================
__global__ void gate_gemm(const float* __restrict__ x,
                          const float* __restrict__ gW,
                          const float* __restrict__ gb) {
    __shared__ float As[16][68];
    __shared__ float Bs[16][64];
    const int tid = threadIdx.x;
    const int i0 = blockIdx.y * 64;
    const int j0 = blockIdx.x * 64;
    const int tx = tid & 15;
    const int ty = tid >> 4;

    float acc[4][4];
#pragma unroll
    for (int r = 0; r < 4; r++)
#pragma unroll
        for (int c = 0; c < 4; c++) acc[r][c] = 0.f;

    for (int k0 = 0; k0 < DD; k0 += 16) {
#pragma unroll
        for (int t = 0; t < 4; t++) {
            int m = tid + t * 256;
            int r = m >> 4, c = m & 15;
            As[c][r] = x[(size_t)(i0 + r) * DD + k0 + c];
        }
#pragma unroll
        for (int t = 0; t < 4; t++) {
            int m = tid + t * 256;
            int r = m >> 6, c = m & 63;
            Bs[r][c] = gW[(size_t)(k0 + r) * EE + j0 + c];
        }
        __syncthreads();
#pragma unroll
        for (int k = 0; k < 16; k++) {
            float a[4], b[4];
#pragma unroll
            for (int r = 0; r < 4; r++) a[r] = As[k][ty * 4 + r];
#pragma unroll
            for (int c = 0; c < 4; c++) b[c] = Bs[k][tx * 4 + c];
#pragma unroll
            for (int r = 0; r < 4; r++)
#pragma unroll
                for (int c = 0; c < 4; c++) acc[r][c] += a[r] * b[c];
        }
        __syncthreads();
    }

#pragma unroll
    for (int r = 0; r < 4; r++) {
        int gi = i0 + ty * 4 + r;
        int gj = j0 + tx * 4;
        float4 v;
        v.x = acc[r][0] + gb[gj + 0];
        v.y = acc[r][1] + gb[gj + 1];
        v.z = acc[r][2] + gb[gj + 2];
        v.w = acc[r][3] + gb[gj + 3];
        *(float4*)&g_w[(size_t)gi * EE + gj] = v;
    }
}

// ============================================================
// Kernel 2: row softmax in-place on g_w
// ============================================================
__global__ void softmax_rows() {
    const int row = blockIdx.x;
    const int tid = threadIdx.x;
    const int lane = tid & 31;
    const int wid = tid >> 5;
    float4* p = ((float4*)g_w) + (size_t)row * (EE / 4);
    float4 v = p[tid];

    __shared__ float red[8];
    __shared__ float bc;

    float m = fmaxf(fmaxf(v.x, v.y), fmaxf(v.z, v.w));
#pragma unroll
    for (int o = 16; o > 0; o >>= 1) m = fmaxf(m, __shfl_xor_sync(0xffffffffu, m, o));
    if (lane == 0) red[wid] = m;
    __syncthreads();
    if (tid == 0) {
        float t = red[0];
#pragma unroll
        for (int i = 1; i < 8; i++) t = fmaxf(t, red[i]);
        bc = t;
    }
    __syncthreads();
    m = bc;
    __syncthreads();

    v.x = expf(v.x - m); v.y = expf(v.y - m);
    v.z = expf(v.z - m); v.w = expf(v.w - m);
    float s = v.x + v.y + v.z + v.w;
#pragma unroll
    for (int o = 16; o > 0; o >>= 1) s += __shfl_xor_sync(0xffffffffu, s, o);
    if (lane == 0) red[wid] = s;
    __syncthreads();
    if (tid == 0) {
        float t = 0.f;
#pragma unroll
        for (int i = 0; i < 8; i++) t += red[i];
        bc = t;
    }
    __syncthreads();
    float inv = 1.f / bc;
    v.x *= inv; v.y *= inv; v.z *= inv; v.w *= inv;
    p[tid] = v;
}

// ============================================================
// Kernel 3: split-K W_eff partials (R1-proven shape) + b_eff fold.
// grid (DD/DT=16, ESPLIT=32), 256 threads, thread owns f4=tid.
// ============================================================
__global__ void weff_partial(const float* __restrict__ eW,
                             const float* __restrict__ eb) {
    const int tid = threadIdx.x;
    const int d0 = blockIdx.x * DT;
    const int es = blockIdx.y;
    const int e0 = es * ECHUNK;
    const bool doB = (blockIdx.x == 0);

    float4 acc[DT];
#pragma unroll
    for (int i = 0; i < DT; i++) acc[i] = make_float4(0.f, 0.f, 0.f, 0.f);
    float4 bacc = make_float4(0.f, 0.f, 0.f, 0.f);

    const float4* wbase = ((const float4*)g_w) + (size_t)e0 * (FF / 4) + tid;
    const float4* ebase = ((const float4*)eW) + ((size_t)e0 * DD + d0) * (FF / 4) + tid;
    const float4* bbase = ((const float4*)eb) + (size_t)e0 * (FF / 4) + tid;

    for (int e = 0; e < ECHUNK; e++) {
        float4 wv = wbase[(size_t)e * (FF / 4)];
        if (doB) {
            float4 bv = bbase[(size_t)e * (FF / 4)];
            bacc.x += wv.x * bv.x; bacc.y += wv.y * bv.y;
            bacc.z += wv.z * bv.z; bacc.w += wv.w * bv.w;
        }
        const float4* ep = ebase + (size_t)e * DD * (FF / 4);
#pragma unroll
        for (int dd = 0; dd < DT; dd++) {
            float4 ev = ep[(size_t)dd * (FF / 4)];
            acc[dd].x += wv.x * ev.x;
            acc[dd].y += wv.y * ev.y;
            acc[dd].z += wv.z * ev.z;
            acc[dd].w += wv.w * ev.w;
        }
    }

    float4* outp = ((float4*)g_part) + ((size_t)es * DD + d0) * (FF / 4) + tid;
#pragma unroll
    for (int dd = 0; dd < DT; dd++) outp[(size_t)dd * (FF / 4)] = acc[dd];
    if (doB) ((float4*)g_bpart)[(size_t)es * (FF / 4) + tid] = bacc;
}

// ============================================================
// Kernel 4: deterministic fixed-order reduction of partials.
// ============================================================
__global__ void reduce_parts() {
    const int idx = blockIdx.x * blockDim.x + threadIdx.x;
    if (idx < DD * FF / 4) {
        float4 s = make_float4(0.f, 0.f, 0.f, 0.f);
#pragma unroll 4
        for (int p = 0; p < ESPLIT; p++) {
            float4 v = ((const float4*)g_part)[(size_t)p * (DD * FF / 4) + idx];
            s.x += v.x; s.y += v.y; s.z += v.z; s.w += v.w;
        }
        ((float4*)g_Weff)[idx] = s;
    }
    if (idx < FF / 4) {
        float4 s = make_float4(0.f, 0.f, 0.f, 0.f);
#pragma unroll 4
        for (int p = 0; p < ESPLIT; p++) {
            float4 v = ((const float4*)g_bpart)[(size_t)p * (FF / 4) + idx];
            s.x += v.x; s.y += v.y; s.z += v.z; s.w += v.w;
        }
        ((float4*)g_beff)[idx] = s;
    }
}

// ============================================================
// Kernel 5: final GEMM via tf32 tensor cores (mma.sync.m16n8k8).
// out = x @ W_eff + b_eff.  CTA tile 128x128, 8 warps (4m x 2n),
// warp tile 32x64 (2 m16-tiles x 8 n8-tiles). BK=32.
// smem rows padded to 136 floats -> conflict-free fragment LDS.
// ============================================================
__device__ __forceinline__ unsigned f2tf32(float x) {
    unsigned u;
    asm("cvt.rna.tf32.f32 %0, %1;" : "=r"(u) : "f"(x));
    return u;
}
__device__ __forceinline__ void mma_tf32(float* d,
                                         const unsigned* a,
                                         const unsigned* b) {
    asm volatile(
        "mma.sync.aligned.m16n8k8.row.col.f32.tf32.tf32.f32 "
        "{%0,%1,%2,%3}, {%4,%5,%6,%7}, {%8,%9}, {%0,%1,%2,%3};\n"
        : "+f"(d[0]), "+f"(d[1]), "+f"(d[2]), "+f"(d[3])
        : "r"(a[0]), "r"(a[1]), "r"(a[2]), "r"(a[3]),
          "r"(b[0]), "r"(b[1]));
}

__global__ void __launch_bounds__(256, 2)
final_gemm_tf32(const float* __restrict__ x, float* __restrict__ out) {
    __shared__ __align__(16) float As[32][136];   // [k][m]
    __shared__ __align__(16) float Bs[32][136];   // [k][n]
    const int tid = threadIdx.x;
    const int wid = tid >> 5;
    const int lane = tid & 31;
    const int g = lane >> 2;        // 0..7
    const int tig = lane & 3;       // 0..3
    const int i0 = blockIdx.y * 128;
    const int j0 = blockIdx.x * 128;
    const int wm = (wid >> 1) * 32; // 0,32,64,96
    const int wn = (wid & 1) * 64;  // 0,64

    float acc[2][8][4];
#pragma unroll
    for (int mt = 0; mt < 2; mt++)
#pragma unroll
        for (int nt = 0; nt < 8; nt++)
#pragma unroll
            for (int r = 0; r < 4; r++) acc[mt][nt][r] = 0.f;

    const int arow = tid >> 1;
    const int akc = (tid & 1) * 16;

    for (int k0 = 0; k0 < DD; k0 += 32) {
        // A tile: x[i0..i0+127][k0..k0+31] -> As[k][m] (transposed store)
#pragma unroll
        for (int t = 0; t < 4; t++) {
            float4 v = *(const float4*)&x[(size_t)(i0 + arow) * DD + k0 + akc + t * 4];
            As[akc + t * 4 + 0][arow] = v.x;
            As[akc + t * 4 + 1][arow] = v.y;
            As[akc + t * 4 + 2][arow] = v.z;
            As[akc + t * 4 + 3][arow] = v.w;
        }
        // B tile: g_Weff[k0..k0+31][j0..j0+127] -> Bs[k][n]
#pragma unroll
        for (int t = 0; t < 4; t++) {
            int f4id = tid + t * 256;
            int kk = f4id >> 5;
            int nc = (f4id & 31) * 4;
            *(float4*)&Bs[kk][nc] = *(const float4*)&g_Weff[(size_t)(k0 + kk) * FF + j0 + nc];
        }
        __syncthreads();

#pragma unroll
        for (int ks = 0; ks < 32; ks += 8) {
            unsigned af[2][4];
#pragma unroll
            for (int mt = 0; mt < 2; mt++) {
                int m0 = wm + mt * 16;
                af[mt][0] = f2tf32(As[ks + tig][m0 + g]);
                af[mt][1] = f2tf32(As[ks + tig][m0 + g + 8]);
                af[mt][2] = f2tf32(As[ks + tig + 4][m0 + g]);
                af[mt][3] = f2tf32(As[ks + tig + 4][m0 + g + 8]);
            }
            unsigned bf[8][2];
#pragma unroll
            for (int nt = 0; nt < 8; nt++) {
                int n0 = wn + nt * 8;
                bf[nt][0] = f2tf32(Bs[ks + tig][n0 + g]);
                bf[nt][1] = f2tf32(Bs[ks + tig + 4][n0 + g]);
            }
#pragma unroll
            for (int mt = 0; mt < 2; mt++)
#pragma unroll
                for (int nt = 0; nt < 8; nt++)
                    mma_tf32(acc[mt][nt], af[mt], bf[nt]);
        }
        __syncthreads();
    }

    // epilogue: bias + store (2 rows per mtile, float2 per reg pair)
#pragma unroll
    for (int mt = 0; mt < 2; mt++) {
        int gi = i0 + wm + mt * 16 + g;
#pragma unroll
        for (int nt = 0; nt < 8; nt++) {
            int gj = j0 + wn + nt * 8 + tig * 2;
            float bx = g_beff[gj];
            float by = g_beff[gj + 1];
            float2 v0, v1;
            v0.x = acc[mt][nt][0] + bx;
            v0.y = acc[mt][nt][1] + by;
            v1.x = acc[mt][nt][2] + bx;
            v1.y = acc[mt][nt][3] + by;
            *(float2*)&out[(size_t)gi * FF + gj] = v0;
            *(float2*)&out[(size_t)(gi + 8) * FF + gj] = v1;
        }
    }
}

// ============================================================
extern "C" void kernel_launch(void* const* d_in, const int* in_sizes, int n_in,
                              void* d_out, int out_size) {
    const float* x  = (const float*)d_in[0];   // (4096, 256)
    const float* gW = (const float*)d_in[1];   // (256, 1024)
    const float* gb = (const float*)d_in[2];   // (1024,)
    const float* eW = (const float*)d_in[3];   // (1024, 256, 1024)
    const float* eb = (const float*)d_in[4];   // (1024, 1024)
    float* out = (float*)d_out;                // (4096, 1024)

    gate_gemm<<<dim3(EE / 64, EE / 64), 256>>>(x, gW, gb);
    softmax_rows<<<EE, 256>>>();
    weff_partial<<<dim3(DD / DT, ESPLIT), 256>>>(eW, eb);
    reduce_parts<<<(DD * FF / 4) / 256, 256>>>();
    final_gemm_tf32<<<dim3(FF / 128, NROWS / 128), 256>>>(x, out);
}

// round 6
// speedup vs baseline: 1.6972x; 1.0311x over previous
#include <cuda_runtime.h>
#include <math.h>

#define DD 256      // D
#define EE 1024     // E
#define FF 1024     // F = 4*D
#define NROWS 4096  // N
#define ESPLIT 32
#define ECHUNK (EE / ESPLIT)   // 32
#define DT 16
#define P4 (DD * FF / 4)       // 65536 float4 outputs of W_eff

// ---- static scratch (no allocations allowed) ----
__device__ float g_w[EE * EE];                          // 4 MB: softmax gate weights
__device__ float g_part[(size_t)ESPLIT * DD * FF];      // 32 MB: split-K partials
__device__ float g_bpart[ESPLIT * FF];                  // 128 KB
__device__ float g_Weff[DD * FF];                       // 1 MB
__device__ float g_beff[FF];                            // 4 KB

// ============================================================
// tf32 helpers
// ============================================================
__device__ __forceinline__ float f2tf32f(float x) {
    unsigned u;
    asm("cvt.rna.tf32.f32 %0, %1;" : "=r"(u) : "f"(x));
    return __uint_as_float(u);
}
__device__ __forceinline__ void mma_tf32(float* d,
                                         const unsigned* a,
                                         const unsigned* b) {
    asm volatile(
        "mma.sync.aligned.m16n8k8.row.col.f32.tf32.tf32.f32 "
        "{%0,%1,%2,%3}, {%4,%5,%6,%7}, {%8,%9}, {%0,%1,%2,%3};\n"
        : "+f"(d[0]), "+f"(d[1]), "+f"(d[2]), "+f"(d[3])
        : "r"(a[0]), "r"(a[1]), "r"(a[2]), "r"(a[3]),
          "r"(b[0]), "r"(b[1]));
}

// ============================================================
// Unified tf32 GEMM:  C[M,1024] = A[M,256] @ B[256,1024] + bias
// CTA tile 128x128, 8 warps (4m x 2n), warp tile 32x64, BK=32.
// tf32 rounding applied ONCE at smem-store; inner loop pure LDS+MMA.
// MODE 0 (gate):  B,bias from params; C = g_w (device global, bound in
//                 DEVICE code — host cannot pass __device__ symbols!)
// MODE 1 (final): B = g_Weff, bias = g_beff (device globals); C = param.
// ============================================================
template <int MODE>
__global__ void __launch_bounds__(256, 2)
gemm_tf32(const float* __restrict__ A, const float* __restrict__ Bp,
          const float* __restrict__ biasp, float* __restrict__ Cp) {
    const float* B    = (MODE == 0) ? Bp    : (const float*)g_Weff;
    const float* bias = (MODE == 0) ? biasp : (const float*)g_beff;
    float*       C    = (MODE == 0) ? (float*)g_w : Cp;

    __shared__ __align__(16) float As[32][136];   // [k][m], tf32-rounded
    __shared__ __align__(16) float Bs[32][136];   // [k][n], tf32-rounded
    const int tid = threadIdx.x;
    const int wid = tid >> 5;
    const int lane = tid & 31;
    const int g = lane >> 2;        // 0..7
    const int tig = lane & 3;       // 0..3
    const int i0 = blockIdx.y * 128;
    const int j0 = blockIdx.x * 128;
    const int wm = (wid >> 1) * 32; // 0,32,64,96
    const int wn = (wid & 1) * 64;  // 0,64

    float acc[2][8][4];
#pragma unroll
    for (int mt = 0; mt < 2; mt++)
#pragma unroll
        for (int nt = 0; nt < 8; nt++)
#pragma unroll
            for (int r = 0; r < 4; r++) acc[mt][nt][r] = 0.f;

    const int arow = tid >> 1;
    const int akc = (tid & 1) * 16;

    for (int k0 = 0; k0 < DD; k0 += 32) {
#pragma unroll
        for (int t = 0; t < 4; t++) {
            float4 v = *(const float4*)&A[(size_t)(i0 + arow) * DD + k0 + akc + t * 4];
            As[akc + t * 4 + 0][arow] = f2tf32f(v.x);
            As[akc + t * 4 + 1][arow] = f2tf32f(v.y);
            As[akc + t * 4 + 2][arow] = f2tf32f(v.z);
            As[akc + t * 4 + 3][arow] = f2tf32f(v.w);
        }
#pragma unroll
        for (int t = 0; t < 4; t++) {
            int f4id = tid + t * 256;
            int kk = f4id >> 5;
            int nc = (f4id & 31) * 4;
            float4 v = *(const float4*)&B[(size_t)(k0 + kk) * FF + j0 + nc];
            float4 w;
            w.x = f2tf32f(v.x); w.y = f2tf32f(v.y);
            w.z = f2tf32f(v.z); w.w = f2tf32f(v.w);
            *(float4*)&Bs[kk][nc] = w;
        }
        __syncthreads();

#pragma unroll
        for (int ks = 0; ks < 32; ks += 8) {
            unsigned af[2][4];
#pragma unroll
            for (int mt = 0; mt < 2; mt++) {
                int m0 = wm + mt * 16;
                af[mt][0] = __float_as_uint(As[ks + tig][m0 + g]);
                af[mt][1] = __float_as_uint(As[ks + tig][m0 + g + 8]);
                af[mt][2] = __float_as_uint(As[ks + tig + 4][m0 + g]);
                af[mt][3] = __float_as_uint(As[ks + tig + 4][m0 + g + 8]);
            }
            unsigned bf[8][2];
#pragma unroll
            for (int nt = 0; nt < 8; nt++) {
                int n0 = wn + nt * 8;
                bf[nt][0] = __float_as_uint(Bs[ks + tig][n0 + g]);
                bf[nt][1] = __float_as_uint(Bs[ks + tig + 4][n0 + g]);
            }
#pragma unroll
            for (int mt = 0; mt < 2; mt++)
#pragma unroll
                for (int nt = 0; nt < 8; nt++)
                    mma_tf32(acc[mt][nt], af[mt], bf[nt]);
        }
        __syncthreads();
    }

#pragma unroll
    for (int mt = 0; mt < 2; mt++) {
        int gi = i0 + wm + mt * 16 + g;
#pragma unroll
        for (int nt = 0; nt < 8; nt++) {
            int gj = j0 + wn + nt * 8 + tig * 2;
            float bx = bias[gj];
            float by = bias[gj + 1];
            float2 v0, v1;
            v0.x = acc[mt][nt][0] + bx;
            v0.y = acc[mt][nt][1] + by;
            v1.x = acc[mt][nt][2] + bx;
            v1.y = acc[mt][nt][3] + by;
            *(float2*)&C[(size_t)gi * FF + gj] = v0;
            *(float2*)&C[(size_t)(gi + 8) * FF + gj] = v1;
        }
    }
}

// ============================================================
// Kernel 2: row softmax in-place on g_w (1024 rows x 1024)
// ============================================================
__global__ void softmax_rows() {
    const int row = blockIdx.x;
    const int tid = threadIdx.x;
    const int lane = tid & 31;
    const int wid = tid >> 5;
    float4* p = ((float4*)g_w) + (size_t)row * (EE / 4);
    float4 v = p[tid];

    __shared__ float red[8];
    __shared__ float bc;

    float m = fmaxf(fmaxf(v.x, v.y), fmaxf(v.z, v.w));
#pragma unroll
    for (int o = 16; o > 0; o >>= 1) m = fmaxf(m, __shfl_xor_sync(0xffffffffu, m, o));
    if (lane == 0) red[wid] = m;
    __syncthreads();
    if (tid == 0) {
        float t = red[0];
#pragma unroll
        for (int i = 1; i < 8; i++) t = fmaxf(t, red[i]);
        bc = t;
    }
    __syncthreads();
    m = bc;
    __syncthreads();

    v.x = expf(v.x - m); v.y = expf(v.y - m);
    v.z = expf(v.z - m); v.w = expf(v.w - m);
    float s = v.x + v.y + v.z + v.w;
#pragma unroll
    for (int o = 16; o > 0; o >>= 1) s += __shfl_xor_sync(0xffffffffu, s, o);
    if (lane == 0) red[wid] = s;
    __syncthreads();
    if (tid == 0) {
        float t = 0.f;
#pragma unroll
        for (int i = 0; i < 8; i++) t += red[i];
        bc = t;
    }
    __syncthreads();
    float inv = 1.f / bc;
    v.x *= inv; v.y *= inv; v.z *= inv; v.w *= inv;
    p[tid] = v;
}

// ============================================================
// Kernel 3: split-K W_eff partials (R1-proven shape) + b_eff fold.
// grid (DD/DT=16, ESPLIT=32), 256 threads, thread owns f4=tid.
// ============================================================
__global__ void weff_partial(const float* __restrict__ eW,
                             const float* __restrict__ eb) {
    const int tid = threadIdx.x;
    const int d0 = blockIdx.x * DT;
    const int es = blockIdx.y;
    const int e0 = es * ECHUNK;
    const bool doB = (blockIdx.x == 0);

    float4 acc[DT];
#pragma unroll
    for (int i = 0; i < DT; i++) acc[i] = make_float4(0.f, 0.f, 0.f, 0.f);
    float4 bacc = make_float4(0.f, 0.f, 0.f, 0.f);

    const float4* wbase = ((const float4*)g_w) + (size_t)e0 * (FF / 4) + tid;
    const float4* ebase = ((const float4*)eW) + ((size_t)e0 * DD + d0) * (FF / 4) + tid;
    const float4* bbase = ((const float4*)eb) + (size_t)e0 * (FF / 4) + tid;

    for (int e = 0; e < ECHUNK; e++) {
        float4 wv = wbase[(size_t)e * (FF / 4)];
        if (doB) {
            float4 bv = bbase[(size_t)e * (FF / 4)];
            bacc.x += wv.x * bv.x; bacc.y += wv.y * bv.y;
            bacc.z += wv.z * bv.z; bacc.w += wv.w * bv.w;
        }
        const float4* ep = ebase + (size_t)e * DD * (FF / 4);
#pragma unroll
        for (int dd = 0; dd < DT; dd++) {
            float4 ev = ep[(size_t)dd * (FF / 4)];
            acc[dd].x += wv.x * ev.x;
            acc[dd].y += wv.y * ev.y;
            acc[dd].z += wv.z * ev.z;
            acc[dd].w += wv.w * ev.w;
        }
    }

    float4* outp = ((float4*)g_part) + ((size_t)es * DD + d0) * (FF / 4) + tid;
#pragma unroll
    for (int dd = 0; dd < DT; dd++) outp[(size_t)dd * (FF / 4)] = acc[dd];
    if (doB) ((float4*)g_bpart)[(size_t)es * (FF / 4) + tid] = bacc;
}

// ============================================================
// Kernel 4: deterministic reduction, 2 threads per output.
// grid 512 x 256. Pair (t, t+128): halves p=[0,16) / p=[16,32),
// fixed-order combine lo+hi. beff by block 0 (ascending order).
// ============================================================
__global__ void reduce_parts() {
    __shared__ float4 sh[128];
    const int t = threadIdx.x;
    const int lane128 = t & 127;
    const int half = t >> 7;
    const int idx = blockIdx.x * 128 + lane128;

    const float4* src = ((const float4*)g_part) + (size_t)(half * 16) * P4 + idx;
    float4 s = make_float4(0.f, 0.f, 0.f, 0.f);
#pragma unroll
    for (int p = 0; p < 16; p++) {
        float4 v = src[(size_t)p * P4];
        s.x += v.x; s.y += v.y; s.z += v.z; s.w += v.w;
    }
    if (half) sh[lane128] = s;
    __syncthreads();
    if (!half) {
        float4 h = sh[lane128];
        float4 o;
        o.x = s.x + h.x; o.y = s.y + h.y; o.z = s.z + h.z; o.w = s.w + h.w;
        ((float4*)g_Weff)[idx] = o;
    }

    if (blockIdx.x == 0) {
        float4 b = make_float4(0.f, 0.f, 0.f, 0.f);
#pragma unroll
        for (int p = 0; p < ESPLIT; p++) {
            float4 v = ((const float4*)g_bpart)[(size_t)p * (FF / 4) + t];
            b.x += v.x; b.y += v.y; b.z += v.z; b.w += v.w;
        }
        ((float4*)g_beff)[t] = b;
    }
}

// ============================================================
extern "C" void kernel_launch(void* const* d_in, const int* in_sizes, int n_in,
                              void* d_out, int out_size) {
    const float* x  = (const float*)d_in[0];   // (4096, 256)
    const float* gW = (const float*)d_in[1];   // (256, 1024)
    const float* gb = (const float*)d_in[2];   // (1024,)
    const float* eW = (const float*)d_in[3];   // (1024, 256, 1024)
    const float* eb = (const float*)d_in[4];   // (1024, 1024)
    float* out = (float*)d_out;                // (4096, 1024)

    // gate: g_w = x[:1024] @ gate_W + gate_b  (C bound to g_w in device code)
    gemm_tf32<0><<<dim3(FF / 128, EE / 128), 256>>>(x, gW, gb, nullptr);
    softmax_rows<<<EE, 256>>>();
    weff_partial<<<dim3(DD / DT, ESPLIT), 256>>>(eW, eb);
    reduce_parts<<<P4 / 128, 256>>>();
    // final: out = x @ g_Weff + g_beff  (B/bias bound in device code)
    gemm_tf32<1><<<dim3(FF / 128, NROWS / 128), 256>>>(x, nullptr, nullptr, out);
}

// round 8
// speedup vs baseline: 1.8486x; 1.0893x over previous
#include <cuda_runtime.h>
#include <cuda_fp16.h>
#include <math.h>
#include <cstdint>

#define DD 256      // D
#define EE 1024     // E
#define FF 1024     // F
#define NROWS 4096  // N
#define ESPLIT 32
#define ECHUNK (EE / ESPLIT)
#define DT 16
#define P4 (DD * FF / 4)

// ---- static scratch ----
__device__ float g_w[EE * EE];                       // softmax gate weights
__device__ float g_part[(size_t)ESPLIT * DD * FF];   // split-K partials
__device__ float g_bpart[ESPLIT * FF];
__device__ float g_beff[FF];
__device__ __align__(16) __half g_xh[NROWS * DD];    // x in fp16 [m][k]
__device__ __align__(16) __half g_wth[FF * DD];      // W_eff^T fp16 [n][k]

// ============================================================
// tf32 helpers (gate GEMM)
// ============================================================
__device__ __forceinline__ float f2tf32f(float x) {
    unsigned u;
    asm("cvt.rna.tf32.f32 %0, %1;" : "=r"(u) : "f"(x));
    return __uint_as_float(u);
}
__device__ __forceinline__ void mma_tf32(float* d, const unsigned* a, const unsigned* b) {
    asm volatile(
        "mma.sync.aligned.m16n8k8.row.col.f32.tf32.tf32.f32 "
        "{%0,%1,%2,%3}, {%4,%5,%6,%7}, {%8,%9}, {%0,%1,%2,%3};\n"
        : "+f"(d[0]), "+f"(d[1]), "+f"(d[2]), "+f"(d[3])
        : "r"(a[0]), "r"(a[1]), "r"(a[2]), "r"(a[3]), "r"(b[0]), "r"(b[1]));
}
// fp16 HMMA m16n8k16, fp32 accumulate
__device__ __forceinline__ void mma_f16(float* d, const unsigned* a, const unsigned* b) {
    asm volatile(
        "mma.sync.aligned.m16n8k16.row.col.f32.f16.f16.f32 "
        "{%0,%1,%2,%3}, {%4,%5,%6,%7}, {%8,%9}, {%0,%1,%2,%3};\n"
        : "+f"(d[0]), "+f"(d[1]), "+f"(d[2]), "+f"(d[3])
        : "r"(a[0]), "r"(a[1]), "r"(a[2]), "r"(a[3]), "r"(b[0]), "r"(b[1]));
}

// ============================================================
// Kernel 1: gate GEMM (tf32, R6-proven). C = g_w (device-bound).
// ============================================================
__global__ void __launch_bounds__(256, 2)
gate_tf32(const float* __restrict__ A, const float* __restrict__ B,
          const float* __restrict__ bias) {
    float* C = (float*)g_w;
    __shared__ __align__(16) float As[32][136];
    __shared__ __align__(16) float Bs[32][136];
    const int tid = threadIdx.x;
    const int wid = tid >> 5;
    const int lane = tid & 31;
    const int g = lane >> 2;
    const int tig = lane & 3;
    const int i0 = blockIdx.y * 128;
    const int j0 = blockIdx.x * 128;
    const int wm = (wid >> 1) * 32;
    const int wn = (wid & 1) * 64;

    float acc[2][8][4];
#pragma unroll
    for (int mt = 0; mt < 2; mt++)
#pragma unroll
        for (int nt = 0; nt < 8; nt++)
#pragma unroll
            for (int r = 0; r < 4; r++) acc[mt][nt][r] = 0.f;

    const int arow = tid >> 1;
    const int akc = (tid & 1) * 16;

    for (int k0 = 0; k0 < DD; k0 += 32) {
#pragma unroll
        for (int t = 0; t < 4; t++) {
            float4 v = *(const float4*)&A[(size_t)(i0 + arow) * DD + k0 + akc + t * 4];
            As[akc + t * 4 + 0][arow] = f2tf32f(v.x);
            As[akc + t * 4 + 1][arow] = f2tf32f(v.y);
            As[akc + t * 4 + 2][arow] = f2tf32f(v.z);
            As[akc + t * 4 + 3][arow] = f2tf32f(v.w);
        }
#pragma unroll
        for (int t = 0; t < 4; t++) {
            int f4id = tid + t * 256;
            int kk = f4id >> 5;
            int nc = (f4id & 31) * 4;
            float4 v = *(const float4*)&B[(size_t)(k0 + kk) * FF + j0 + nc];
            float4 w;
            w.x = f2tf32f(v.x); w.y = f2tf32f(v.y);
            w.z = f2tf32f(v.z); w.w = f2tf32f(v.w);
            *(float4*)&Bs[kk][nc] = w;
        }
        __syncthreads();
#pragma unroll
        for (int ks = 0; ks < 32; ks += 8) {
            unsigned af[2][4];
#pragma unroll
            for (int mt = 0; mt < 2; mt++) {
                int m0 = wm + mt * 16;
                af[mt][0] = __float_as_uint(As[ks + tig][m0 + g]);
                af[mt][1] = __float_as_uint(As[ks + tig][m0 + g + 8]);
                af[mt][2] = __float_as_uint(As[ks + tig + 4][m0 + g]);
                af[mt][3] = __float_as_uint(As[ks + tig + 4][m0 + g + 8]);
            }
            unsigned bf[8][2];
#pragma unroll
            for (int nt = 0; nt < 8; nt++) {
                int n0 = wn + nt * 8;
                bf[nt][0] = __float_as_uint(Bs[ks + tig][n0 + g]);
                bf[nt][1] = __float_as_uint(Bs[ks + tig + 4][n0 + g]);
            }
#pragma unroll
            for (int mt = 0; mt < 2; mt++)
#pragma unroll
                for (int nt = 0; nt < 8; nt++)
                    mma_tf32(acc[mt][nt], af[mt], bf[nt]);
        }
        __syncthreads();
    }
#pragma unroll
    for (int mt = 0; mt < 2; mt++) {
        int gi = i0 + wm + mt * 16 + g;
#pragma unroll
        for (int nt = 0; nt < 8; nt++) {
            int gj = j0 + wn + nt * 8 + tig * 2;
            float bx = bias[gj], by = bias[gj + 1];
            float2 v0, v1;
            v0.x = acc[mt][nt][0] + bx; v0.y = acc[mt][nt][1] + by;
            v1.x = acc[mt][nt][2] + bx; v1.y = acc[mt][nt][3] + by;
            *(float2*)&C[(size_t)gi * FF + gj] = v0;
            *(float2*)&C[(size_t)(gi + 8) * FF + gj] = v1;
        }
    }
}

// ============================================================
// Kernel 2: row softmax on g_w
// ============================================================
__global__ void softmax_rows() {
    const int row = blockIdx.x;
    const int tid = threadIdx.x;
    const int lane = tid & 31;
    const int wid = tid >> 5;
    float4* p = ((float4*)g_w) + (size_t)row * (EE / 4);
    float4 v = p[tid];
    __shared__ float red[8];
    __shared__ float bc;

    float m = fmaxf(fmaxf(v.x, v.y), fmaxf(v.z, v.w));
#pragma unroll
    for (int o = 16; o > 0; o >>= 1) m = fmaxf(m, __shfl_xor_sync(0xffffffffu, m, o));
    if (lane == 0) red[wid] = m;
    __syncthreads();
    if (tid == 0) {
        float t = red[0];
#pragma unroll
        for (int i = 1; i < 8; i++) t = fmaxf(t, red[i]);
        bc = t;
    }
    __syncthreads();
    m = bc;
    __syncthreads();
    v.x = expf(v.x - m); v.y = expf(v.y - m);
    v.z = expf(v.z - m); v.w = expf(v.w - m);
    float s = v.x + v.y + v.z + v.w;
#pragma unroll
    for (int o = 16; o > 0; o >>= 1) s += __shfl_xor_sync(0xffffffffu, s, o);
    if (lane == 0) red[wid] = s;
    __syncthreads();
    if (tid == 0) {
        float t = 0.f;
#pragma unroll
        for (int i = 0; i < 8; i++) t += red[i];
        bc = t;
    }
    __syncthreads();
    float inv = 1.f / bc;
    v.x *= inv; v.y *= inv; v.z *= inv; v.w *= inv;
    p[tid] = v;
}

// ============================================================
// Kernel 3: x -> fp16 (8 floats / thread)
// ============================================================
__global__ void cvt_x(const float* __restrict__ x) {
    const int idx = blockIdx.x * 256 + threadIdx.x;   // per 8 elems
    float4 v0 = ((const float4*)x)[idx * 2];
    float4 v1 = ((const float4*)x)[idx * 2 + 1];
    __half2 h[4];
    h[0] = __floats2half2_rn(v0.x, v0.y);
    h[1] = __floats2half2_rn(v0.z, v0.w);
    h[2] = __floats2half2_rn(v1.x, v1.y);
    h[3] = __floats2half2_rn(v1.z, v1.w);
    ((uint4*)g_xh)[idx] = *(uint4*)h;
}

// ============================================================
// Kernel 4: split-K W_eff partials + b_eff fold (__ldcs stream).
// ============================================================
__global__ void weff_partial(const float* __restrict__ eW,
                             const float* __restrict__ eb) {
    const int tid = threadIdx.x;
    const int d0 = blockIdx.x * DT;
    const int es = blockIdx.y;
    const int e0 = es * ECHUNK;
    const bool doB = (blockIdx.x == 0);

    float4 acc[DT];
#pragma unroll
    for (int i = 0; i < DT; i++) acc[i] = make_float4(0.f, 0.f, 0.f, 0.f);
    float4 bacc = make_float4(0.f, 0.f, 0.f, 0.f);

    const float4* wbase = ((const float4*)g_w) + (size_t)e0 * (FF / 4) + tid;
    const float4* ebase = ((const float4*)eW) + ((size_t)e0 * DD + d0) * (FF / 4) + tid;
    const float4* bbase = ((const float4*)eb) + (size_t)e0 * (FF / 4) + tid;

    for (int e = 0; e < ECHUNK; e++) {
        float4 wv = wbase[(size_t)e * (FF / 4)];
        if (doB) {
            float4 bv = __ldcs(bbase + (size_t)e * (FF / 4));
            bacc.x += wv.x * bv.x; bacc.y += wv.y * bv.y;
            bacc.z += wv.z * bv.z; bacc.w += wv.w * bv.w;
        }
        const float4* ep = ebase + (size_t)e * DD * (FF / 4);
#pragma unroll
        for (int dd = 0; dd < DT; dd++) {
            float4 ev = __ldcs(ep + (size_t)dd * (FF / 4));
            acc[dd].x += wv.x * ev.x;
            acc[dd].y += wv.y * ev.y;
            acc[dd].z += wv.z * ev.z;
            acc[dd].w += wv.w * ev.w;
        }
    }
    float4* outp = ((float4*)g_part) + ((size_t)es * DD + d0) * (FF / 4) + tid;
#pragma unroll
    for (int dd = 0; dd < DT; dd++) outp[(size_t)dd * (FF / 4)] = acc[dd];
    if (doB) ((float4*)g_bpart)[(size_t)es * (FF / 4) + tid] = bacc;
}

// ============================================================
// Kernel 5: deterministic reduce -> emit W_eff^T fp16 [f][d] + beff.
// Block covers fixed d, 512 consecutive f.
// ============================================================
__global__ void reduce_parts() {
    __shared__ float4 sh[128];
    const int t = threadIdx.x;
    const int lane128 = t & 127;
    const int half_ = t >> 7;
    const int idx = blockIdx.x * 128 + lane128;

    const float4* src = ((const float4*)g_part) + (size_t)(half_ * 16) * P4 + idx;
    float4 s = make_float4(0.f, 0.f, 0.f, 0.f);
#pragma unroll
    for (int p = 0; p < 16; p++) {
        float4 v = src[(size_t)p * P4];
        s.x += v.x; s.y += v.y; s.z += v.z; s.w += v.w;
    }
    if (half_) sh[lane128] = s;
    __syncthreads();
    if (!half_) {
        float4 h = sh[lane128];
        float vals[4];
        vals[0] = s.x + h.x; vals[1] = s.y + h.y;
        vals[2] = s.z + h.z; vals[3] = s.w + h.w;
        const int d = idx >> 8;            // k index
        const int f = (idx & 255) * 4;     // n base
#pragma unroll
        for (int j = 0; j < 4; j++)
            g_wth[(size_t)(f + j) * DD + d] = __float2half_rn(vals[j]);
    }
    if (blockIdx.x == 0) {
        float4 b = make_float4(0.f, 0.f, 0.f, 0.f);
#pragma unroll
        for (int p = 0; p < ESPLIT; p++) {
            float4 v = ((const float4*)g_bpart)[(size_t)p * (FF / 4) + t];
            b.x += v.x; b.y += v.y; b.z += v.z; b.w += v.w;
        }
        ((float4*)g_beff)[t] = b;
    }
}

// ============================================================
// Kernel 6: final GEMM, fp16 HMMA m16n8k16, fp32 accumulate.
// out[4096,1024] = x @ W_eff + b_eff.
// CTA 128x128, 8 warps (4m x 2n), warp tile 32x64, BK=64.
// As[m][k], Bs[n][k], rows padded to 72 halfs (conflict-free frags).
// ============================================================
__global__ void __launch_bounds__(256, 2)
final_hmma(float* __restrict__ out) {
    __shared__ __align__(16) __half As[128][72];
    __shared__ __align__(16) __half Bs[128][72];
    const int tid = threadIdx.x;
    const int wid = tid >> 5;
    const int lane = tid & 31;
    const int g = lane >> 2;
    const int tig = lane & 3;
    const int i0 = blockIdx.y * 128;
    const int j0 = blockIdx.x * 128;
    const int wm = (wid >> 1) * 32;
    const int wn = (wid & 1) * 64;

    float acc[2][8][4];
#pragma unroll
    for (int mt = 0; mt < 2; mt++)
#pragma unroll
        for (int nt = 0; nt < 8; nt++)
#pragma unroll
            for (int r = 0; r < 4; r++) acc[mt][nt][r] = 0.f;

    for (int kc = 0; kc < DD; kc += 64) {
        // A tile: 128 rows x 64 halfs (8 uint4/row); 4 uint4/thread
#pragma unroll
        for (int t = 0; t < 4; t++) {
            int idx = tid + t * 256;
            int r = idx >> 3, c8 = idx & 7;
            *(uint4*)&As[r][c8 * 8] =
                *(const uint4*)(g_xh + (size_t)(i0 + r) * DD + kc + c8 * 8);
        }
        // B tile: W^T rows (n) x 64 halfs of k
#pragma unroll
        for (int t = 0; t < 4; t++) {
            int idx = tid + t * 256;
            int r = idx >> 3, c8 = idx & 7;
            *(uint4*)&Bs[r][c8 * 8] =
                *(const uint4*)(g_wth + (size_t)(j0 + r) * DD + kc + c8 * 8);
        }
        __syncthreads();

#pragma unroll
        for (int ks = 0; ks < 64; ks += 16) {
            unsigned af[2][4];
#pragma unroll
            for (int mt = 0; mt < 2; mt++) {
                int m0 = wm + mt * 16;
                af[mt][0] = *(const unsigned*)&As[m0 + g][ks + tig * 2];
                af[mt][1] = *(const unsigned*)&As[m0 + g + 8][ks + tig * 2];
                af[mt][2] = *(const unsigned*)&As[m0 + g][ks + tig * 2 + 8];
                af[mt][3] = *(const unsigned*)&As[m0 + g + 8][ks + tig * 2 + 8];
            }
            unsigned bf[8][2];
#pragma unroll
            for (int nt = 0; nt < 8; nt++) {
                int n0 = wn + nt * 8;
                bf[nt][0] = *(const unsigned*)&Bs[n0 + g][ks + tig * 2];
                bf[nt][1] = *(const unsigned*)&Bs[n0 + g][ks + tig * 2 + 8];
            }
#pragma unroll
            for (int mt = 0; mt < 2; mt++)
#pragma unroll
                for (int nt = 0; nt < 8; nt++)
                    mma_f16(acc[mt][nt], af[mt], bf[nt]);
        }
        __syncthreads();
    }

#pragma unroll
    for (int mt = 0; mt < 2; mt++) {
        int gi = i0 + wm + mt * 16 + g;
#pragma unroll
        for (int nt = 0; nt < 8; nt++) {
            int gj = j0 + wn + nt * 8 + tig * 2;
            float bx = g_beff[gj], by = g_beff[gj + 1];
            float2 v0, v1;
            v0.x = acc[mt][nt][0] + bx; v0.y = acc[mt][nt][1] + by;
            v1.x = acc[mt][nt][2] + bx; v1.y = acc[mt][nt][3] + by;
            *(float2*)&out[(size_t)gi * FF + gj] = v0;
            *(float2*)&out[(size_t)(gi + 8) * FF + gj] = v1;
        }
    }
}

// ============================================================
extern "C" void kernel_launch(void* const* d_in, const int* in_sizes, int n_in,
                              void* d_out, int out_size) {
    const float* x  = (const float*)d_in[0];   // (4096, 256)
    const float* gW = (const float*)d_in[1];   // (256, 1024)
    const float* gb = (const float*)d_in[2];   // (1024,)
    const float* eW = (const float*)d_in[3];   // (1024, 256, 1024)
    const float* eb = (const float*)d_in[4];   // (1024, 1024)
    float* out = (float*)d_out;                // (4096, 1024)

    cvt_x<<<NROWS * DD / 8 / 256, 256>>>(x);
    gate_tf32<<<dim3(FF / 128, EE / 128), 256>>>(x, gW, gb);
    softmax_rows<<<EE, 256>>>();
    weff_partial<<<dim3(DD / DT, ESPLIT), 256>>>(eW, eb);
    reduce_parts<<<P4 / 128, 256>>>();
    final_hmma<<<dim3(FF / 128, NROWS / 128), 256>>>(out);
}

// round 9
// speedup vs baseline: 2.0144x; 1.0897x over previous
#include <cuda_runtime.h>
#include <cuda_fp16.h>
#include <math.h>
#include <cstdint>

#define DD 256      // D
#define EE 1024     // E
#define FF 1024     // F
#define NROWS 4096  // N
#define NCHUNK 18   // e-chunks: 16 d-tiles x 18 = 288 CTAs = ONE wave @2 CTA/SM
#define DT 16
#define P4 (DD * FF / 4)

// ---- static scratch ----
__device__ float g_w[EE * EE];                        // softmax gate weights
__device__ float g_part[(size_t)NCHUNK * DD * FF];    // 18 MB split-K partials
__device__ float g_bpart[NCHUNK * FF];
__device__ float g_beff[FF];
__device__ __align__(16) __half g_xh[NROWS * DD];     // x in fp16 [m][k]
__device__ __align__(16) __half g_wth[FF * DD];       // W_eff^T fp16 [n][k]

// ============================================================
// mma helpers
// ============================================================
__device__ __forceinline__ float f2tf32f(float x) {
    unsigned u;
    asm("cvt.rna.tf32.f32 %0, %1;" : "=r"(u) : "f"(x));
    return __uint_as_float(u);
}
__device__ __forceinline__ void mma_tf32(float* d, const unsigned* a, const unsigned* b) {
    asm volatile(
        "mma.sync.aligned.m16n8k8.row.col.f32.tf32.tf32.f32 "
        "{%0,%1,%2,%3}, {%4,%5,%6,%7}, {%8,%9}, {%0,%1,%2,%3};\n"
        : "+f"(d[0]), "+f"(d[1]), "+f"(d[2]), "+f"(d[3])
        : "r"(a[0]), "r"(a[1]), "r"(a[2]), "r"(a[3]), "r"(b[0]), "r"(b[1]));
}
__device__ __forceinline__ void mma_f16(float* d, const unsigned* a, const unsigned* b) {
    asm volatile(
        "mma.sync.aligned.m16n8k16.row.col.f32.f16.f16.f32 "
        "{%0,%1,%2,%3}, {%4,%5,%6,%7}, {%8,%9}, {%0,%1,%2,%3};\n"
        : "+f"(d[0]), "+f"(d[1]), "+f"(d[2]), "+f"(d[3])
        : "r"(a[0]), "r"(a[1]), "r"(a[2]), "r"(a[3]), "r"(b[0]), "r"(b[1]));
}

// ============================================================
// Kernel 1: gate GEMM (tf32, proven). C = g_w (device-bound).
// ============================================================
__global__ void __launch_bounds__(256, 2)
gate_tf32(const float* __restrict__ A, const float* __restrict__ B,
          const float* __restrict__ bias) {
    float* C = (float*)g_w;
    __shared__ __align__(16) float As[32][136];
    __shared__ __align__(16) float Bs[32][136];
    const int tid = threadIdx.x;
    const int wid = tid >> 5;
    const int lane = tid & 31;
    const int g = lane >> 2;
    const int tig = lane & 3;
    const int i0 = blockIdx.y * 128;
    const int j0 = blockIdx.x * 128;
    const int wm = (wid >> 1) * 32;
    const int wn = (wid & 1) * 64;

    float acc[2][8][4];
#pragma unroll
    for (int mt = 0; mt < 2; mt++)
#pragma unroll
        for (int nt = 0; nt < 8; nt++)
#pragma unroll
            for (int r = 0; r < 4; r++) acc[mt][nt][r] = 0.f;

    const int arow = tid >> 1;
    const int akc = (tid & 1) * 16;

    for (int k0 = 0; k0 < DD; k0 += 32) {
#pragma unroll
        for (int t = 0; t < 4; t++) {
            float4 v = *(const float4*)&A[(size_t)(i0 + arow) * DD + k0 + akc + t * 4];
            As[akc + t * 4 + 0][arow] = f2tf32f(v.x);
            As[akc + t * 4 + 1][arow] = f2tf32f(v.y);
            As[akc + t * 4 + 2][arow] = f2tf32f(v.z);
            As[akc + t * 4 + 3][arow] = f2tf32f(v.w);
        }
#pragma unroll
        for (int t = 0; t < 4; t++) {
            int f4id = tid + t * 256;
            int kk = f4id >> 5;
            int nc = (f4id & 31) * 4;
            float4 v = *(const float4*)&B[(size_t)(k0 + kk) * FF + j0 + nc];
            float4 w;
            w.x = f2tf32f(v.x); w.y = f2tf32f(v.y);
            w.z = f2tf32f(v.z); w.w = f2tf32f(v.w);
            *(float4*)&Bs[kk][nc] = w;
        }
        __syncthreads();
#pragma unroll
        for (int ks = 0; ks < 32; ks += 8) {
            unsigned af[2][4];
#pragma unroll
            for (int mt = 0; mt < 2; mt++) {
                int m0 = wm + mt * 16;
                af[mt][0] = __float_as_uint(As[ks + tig][m0 + g]);
                af[mt][1] = __float_as_uint(As[ks + tig][m0 + g + 8]);
                af[mt][2] = __float_as_uint(As[ks + tig + 4][m0 + g]);
                af[mt][3] = __float_as_uint(As[ks + tig + 4][m0 + g + 8]);
            }
            unsigned bf[8][2];
#pragma unroll
            for (int nt = 0; nt < 8; nt++) {
                int n0 = wn + nt * 8;
                bf[nt][0] = __float_as_uint(Bs[ks + tig][n0 + g]);
                bf[nt][1] = __float_as_uint(Bs[ks + tig + 4][n0 + g]);
            }
#pragma unroll
            for (int mt = 0; mt < 2; mt++)
#pragma unroll
                for (int nt = 0; nt < 8; nt++)
                    mma_tf32(acc[mt][nt], af[mt], bf[nt]);
        }
        __syncthreads();
    }
#pragma unroll
    for (int mt = 0; mt < 2; mt++) {
        int gi = i0 + wm + mt * 16 + g;
#pragma unroll
        for (int nt = 0; nt < 8; nt++) {
            int gj = j0 + wn + nt * 8 + tig * 2;
            float bx = bias[gj], by = bias[gj + 1];
            float2 v0, v1;
            v0.x = acc[mt][nt][0] + bx; v0.y = acc[mt][nt][1] + by;
            v1.x = acc[mt][nt][2] + bx; v1.y = acc[mt][nt][3] + by;
            *(float2*)&C[(size_t)gi * FF + gj] = v0;
            *(float2*)&C[(size_t)(gi + 8) * FF + gj] = v1;
        }
    }
}

// ============================================================
// Kernel 2: row softmax on g_w
// ============================================================
__global__ void softmax_rows() {
    const int row = blockIdx.x;
    const int tid = threadIdx.x;
    const int lane = tid & 31;
    const int wid = tid >> 5;
    float4* p = ((float4*)g_w) + (size_t)row * (EE / 4);
    float4 v = p[tid];
    __shared__ float red[8];
    __shared__ float bc;

    float m = fmaxf(fmaxf(v.x, v.y), fmaxf(v.z, v.w));
#pragma unroll
    for (int o = 16; o > 0; o >>= 1) m = fmaxf(m, __shfl_xor_sync(0xffffffffu, m, o));
    if (lane == 0) red[wid] = m;
    __syncthreads();
    if (tid == 0) {
        float t = red[0];
#pragma unroll
        for (int i = 1; i < 8; i++) t = fmaxf(t, red[i]);
        bc = t;
    }
    __syncthreads();
    m = bc;
    __syncthreads();
    v.x = expf(v.x - m); v.y = expf(v.y - m);
    v.z = expf(v.z - m); v.w = expf(v.w - m);
    float s = v.x + v.y + v.z + v.w;
#pragma unroll
    for (int o = 16; o > 0; o >>= 1) s += __shfl_xor_sync(0xffffffffu, s, o);
    if (lane == 0) red[wid] = s;
    __syncthreads();
    if (tid == 0) {
        float t = 0.f;
#pragma unroll
        for (int i = 0; i < 8; i++) t += red[i];
        bc = t;
    }
    __syncthreads();
    float inv = 1.f / bc;
    v.x *= inv; v.y *= inv; v.z *= inv; v.w *= inv;
    p[tid] = v;
}

// ============================================================
// Kernel 3: x -> fp16 (8 floats / thread)
// ============================================================
__global__ void cvt_x(const float* __restrict__ x) {
    const int idx = blockIdx.x * 256 + threadIdx.x;
    float4 v0 = ((const float4*)x)[idx * 2];
    float4 v1 = ((const float4*)x)[idx * 2 + 1];
    __half2 h[4];
    h[0] = __floats2half2_rn(v0.x, v0.y);
    h[1] = __floats2half2_rn(v0.z, v0.w);
    h[2] = __floats2half2_rn(v1.x, v1.y);
    h[3] = __floats2half2_rn(v1.z, v1.w);
    ((uint4*)g_xh)[idx] = *(uint4*)h;
}

// ============================================================
// Kernel 4: split-K W_eff partials + b_eff fold.
// grid (16 d-tiles, 18 e-chunks) = 288 CTAs = ONE full wave.
// Chunk es covers e in [es*EE/18, (es+1)*EE/18)  (56 or 57 e's).
// eW streamed __ldcs so partials + g_w stay L2-resident.
// ============================================================
__global__ void weff_partial(const float* __restrict__ eW,
                             const float* __restrict__ eb) {
    const int tid = threadIdx.x;
    const int d0 = blockIdx.x * DT;
    const int es = blockIdx.y;
    const int e0 = (es * EE) / NCHUNK;
    const int e1 = ((es + 1) * EE) / NCHUNK;
    const bool doB = (blockIdx.x == 0);

    float4 acc[DT];
#pragma unroll
    for (int i = 0; i < DT; i++) acc[i] = make_float4(0.f, 0.f, 0.f, 0.f);
    float4 bacc = make_float4(0.f, 0.f, 0.f, 0.f);

    const float4* wp = ((const float4*)g_w) + tid;
    const float4* ep = ((const float4*)eW) + (size_t)d0 * (FF / 4) + tid;
    const float4* bp = ((const float4*)eb) + tid;

    for (int e = e0; e < e1; e++) {
        float4 wv = wp[(size_t)e * (FF / 4)];
        if (doB) {
            float4 bv = __ldcs(bp + (size_t)e * (FF / 4));
            bacc.x += wv.x * bv.x; bacc.y += wv.y * bv.y;
            bacc.z += wv.z * bv.z; bacc.w += wv.w * bv.w;
        }
        const float4* ee = ep + (size_t)e * DD * (FF / 4);
#pragma unroll
        for (int dd = 0; dd < DT; dd++) {
            float4 ev = __ldcs(ee + (size_t)dd * (FF / 4));
            acc[dd].x += wv.x * ev.x;
            acc[dd].y += wv.y * ev.y;
            acc[dd].z += wv.z * ev.z;
            acc[dd].w += wv.w * ev.w;
        }
    }
    float4* outp = ((float4*)g_part) + ((size_t)es * DD + d0) * (FF / 4) + tid;
#pragma unroll
    for (int dd = 0; dd < DT; dd++) outp[(size_t)dd * (FF / 4)] = acc[dd];
    if (doB) ((float4*)g_bpart)[(size_t)es * (FF / 4) + tid] = bacc;
}

// ============================================================
// Kernel 5: deterministic reduce over 18 chunks (9 + 9 across
// thread halves, fixed order) -> emit W_eff^T fp16 [f][d] + beff.
// ============================================================
__global__ void reduce_parts() {
    __shared__ float4 sh[128];
    const int t = threadIdx.x;
    const int lane128 = t & 127;
    const int half_ = t >> 7;
    const int idx = blockIdx.x * 128 + lane128;

    const float4* src = ((const float4*)g_part) + (size_t)(half_ * 9) * P4 + idx;
    float4 s = make_float4(0.f, 0.f, 0.f, 0.f);
#pragma unroll
    for (int p = 0; p < 9; p++) {
        float4 v = src[(size_t)p * P4];
        s.x += v.x; s.y += v.y; s.z += v.z; s.w += v.w;
    }
    if (half_) sh[lane128] = s;
    __syncthreads();
    if (!half_) {
        float4 h = sh[lane128];
        float vals[4];
        vals[0] = s.x + h.x; vals[1] = s.y + h.y;
        vals[2] = s.z + h.z; vals[3] = s.w + h.w;
        const int d = idx >> 8;            // k index
        const int f = (idx & 255) * 4;     // n base
#pragma unroll
        for (int j = 0; j < 4; j++)
            g_wth[(size_t)(f + j) * DD + d] = __float2half_rn(vals[j]);
    }
    if (blockIdx.x == 0) {
        float4 b = make_float4(0.f, 0.f, 0.f, 0.f);
#pragma unroll
        for (int p = 0; p < NCHUNK; p++) {
            float4 v = ((const float4*)g_bpart)[(size_t)p * (FF / 4) + t];
            b.x += v.x; b.y += v.y; b.z += v.z; b.w += v.w;
        }
        ((float4*)g_beff)[t] = b;
    }
}

// ============================================================
// Kernel 6: final GEMM, fp16 HMMA m16n8k16, fp32 accumulate.
// CTA 128x128, 8 warps, warp tile 32x64, BK=64. (R8-proven)
// ============================================================
__global__ void __launch_bounds__(256, 2)
final_hmma(float* __restrict__ out) {
    __shared__ __align__(16) __half As[128][72];
    __shared__ __align__(16) __half Bs[128][72];
    const int tid = threadIdx.x;
    const int wid = tid >> 5;
    const int lane = tid & 31;
    const int g = lane >> 2;
    const int tig = lane & 3;
    const int i0 = blockIdx.y * 128;
    const int j0 = blockIdx.x * 128;
    const int wm = (wid >> 1) * 32;
    const int wn = (wid & 1) * 64;

    float acc[2][8][4];
#pragma unroll
    for (int mt = 0; mt < 2; mt++)
#pragma unroll
        for (int nt = 0; nt < 8; nt++)
#pragma unroll
            for (int r = 0; r < 4; r++) acc[mt][nt][r] = 0.f;

    for (int kc = 0; kc < DD; kc += 64) {
#pragma unroll
        for (int t = 0; t < 4; t++) {
            int idx = tid + t * 256;
            int r = idx >> 3, c8 = idx & 7;
            *(uint4*)&As[r][c8 * 8] =
                *(const uint4*)(g_xh + (size_t)(i0 + r) * DD + kc + c8 * 8);
        }
#pragma unroll
        for (int t = 0; t < 4; t++) {
            int idx = tid + t * 256;
            int r = idx >> 3, c8 = idx & 7;
            *(uint4*)&Bs[r][c8 * 8] =
                *(const uint4*)(g_wth + (size_t)(j0 + r) * DD + kc + c8 * 8);
        }
        __syncthreads();

#pragma unroll
        for (int ks = 0; ks < 64; ks += 16) {
            unsigned af[2][4];
#pragma unroll
            for (int mt = 0; mt < 2; mt++) {
                int m0 = wm + mt * 16;
                af[mt][0] = *(const unsigned*)&As[m0 + g][ks + tig * 2];
                af[mt][1] = *(const unsigned*)&As[m0 + g + 8][ks + tig * 2];
                af[mt][2] = *(const unsigned*)&As[m0 + g][ks + tig * 2 + 8];
                af[mt][3] = *(const unsigned*)&As[m0 + g + 8][ks + tig * 2 + 8];
            }
            unsigned bf[8][2];
#pragma unroll
            for (int nt = 0; nt < 8; nt++) {
                int n0 = wn + nt * 8;
                bf[nt][0] = *(const unsigned*)&Bs[n0 + g][ks + tig * 2];
                bf[nt][1] = *(const unsigned*)&Bs[n0 + g][ks + tig * 2 + 8];
            }
#pragma unroll
            for (int mt = 0; mt < 2; mt++)
#pragma unroll
                for (int nt = 0; nt < 8; nt++)
                    mma_f16(acc[mt][nt], af[mt], bf[nt]);
        }
        __syncthreads();
    }

#pragma unroll
    for (int mt = 0; mt < 2; mt++) {
        int gi = i0 + wm + mt * 16 + g;
#pragma unroll
        for (int nt = 0; nt < 8; nt++) {
            int gj = j0 + wn + nt * 8 + tig * 2;
            float bx = g_beff[gj], by = g_beff[gj + 1];
            float2 v0, v1;
            v0.x = acc[mt][nt][0] + bx; v0.y = acc[mt][nt][1] + by;
            v1.x = acc[mt][nt][2] + bx; v1.y = acc[mt][nt][3] + by;
            *(float2*)&out[(size_t)gi * FF + gj] = v0;
            *(float2*)&out[(size_t)(gi + 8) * FF + gj] = v1;
        }
    }
}

// ============================================================
extern "C" void kernel_launch(void* const* d_in, const int* in_sizes, int n_in,
                              void* d_out, int out_size) {
    const float* x  = (const float*)d_in[0];   // (4096, 256)
    const float* gW = (const float*)d_in[1];   // (256, 1024)
    const float* gb = (const float*)d_in[2];   // (1024,)
    const float* eW = (const float*)d_in[3];   // (1024, 256, 1024)
    const float* eb = (const float*)d_in[4];   // (1024, 1024)
    float* out = (float*)d_out;                // (4096, 1024)

    cvt_x<<<NROWS * DD / 8 / 256, 256>>>(x);
    gate_tf32<<<dim3(FF / 128, EE / 128), 256>>>(x, gW, gb);
    softmax_rows<<<EE, 256>>>();
    weff_partial<<<dim3(DD / DT, NCHUNK), 256>>>(eW, eb);
    reduce_parts<<<P4 / 128, 256>>>();
    final_hmma<<<dim3(FF / 128, NROWS / 128), 256>>>(out);
}

// round 10
// speedup vs baseline: 2.1524x; 1.0685x over previous
#include <cuda_runtime.h>
#include <cuda_fp16.h>
#include <math.h>
#include <cstdint>

#define DD 256      // D
#define EE 1024     // E
#define FF 1024     // F
#define NROWS 4096  // N
#define NCHUNK 18   // e-chunks
#define DT 8        // d-rows per CTA: 32 d-tiles x 18 chunks = 576 CTAs = 1 wave @4 CTA/SM
#define P4 (DD * FF / 4)

// ---- static scratch ----
__device__ float g_w[EE * EE];                        // softmax gate weights
__device__ float g_part[(size_t)NCHUNK * DD * FF];    // 18 MB split-K partials
__device__ float g_bpart[NCHUNK * FF];
__device__ float g_beff[FF];
__device__ __align__(16) __half g_xh[NROWS * DD];     // x in fp16 [m][k]
__device__ __align__(16) __half g_wth[FF * DD];       // W_eff^T fp16 [n][k]

// ============================================================
// mma helpers
// ============================================================
__device__ __forceinline__ float f2tf32f(float x) {
    unsigned u;
    asm("cvt.rna.tf32.f32 %0, %1;" : "=r"(u) : "f"(x));
    return __uint_as_float(u);
}
__device__ __forceinline__ void mma_tf32(float* d, const unsigned* a, const unsigned* b) {
    asm volatile(
        "mma.sync.aligned.m16n8k8.row.col.f32.tf32.tf32.f32 "
        "{%0,%1,%2,%3}, {%4,%5,%6,%7}, {%8,%9}, {%0,%1,%2,%3};\n"
        : "+f"(d[0]), "+f"(d[1]), "+f"(d[2]), "+f"(d[3])
        : "r"(a[0]), "r"(a[1]), "r"(a[2]), "r"(a[3]), "r"(b[0]), "r"(b[1]));
}
__device__ __forceinline__ void mma_f16(float* d, const unsigned* a, const unsigned* b) {
    asm volatile(
        "mma.sync.aligned.m16n8k16.row.col.f32.f16.f16.f32 "
        "{%0,%1,%2,%3}, {%4,%5,%6,%7}, {%8,%9}, {%0,%1,%2,%3};\n"
        : "+f"(d[0]), "+f"(d[1]), "+f"(d[2]), "+f"(d[3])
        : "r"(a[0]), "r"(a[1]), "r"(a[2]), "r"(a[3]), "r"(b[0]), "r"(b[1]));
}

// ============================================================
// Kernel 1: gate GEMM (tf32, proven). C = g_w (device-bound).
// ============================================================
__global__ void __launch_bounds__(256, 2)
gate_tf32(const float* __restrict__ A, const float* __restrict__ B,
          const float* __restrict__ bias) {
    float* C = (float*)g_w;
    __shared__ __align__(16) float As[32][136];
    __shared__ __align__(16) float Bs[32][136];
    const int tid = threadIdx.x;
    const int wid = tid >> 5;
    const int lane = tid & 31;
    const int g = lane >> 2;
    const int tig = lane & 3;
    const int i0 = blockIdx.y * 128;
    const int j0 = blockIdx.x * 128;
    const int wm = (wid >> 1) * 32;
    const int wn = (wid & 1) * 64;

    float acc[2][8][4];
#pragma unroll
    for (int mt = 0; mt < 2; mt++)
#pragma unroll
        for (int nt = 0; nt < 8; nt++)
#pragma unroll
            for (int r = 0; r < 4; r++) acc[mt][nt][r] = 0.f;

    const int arow = tid >> 1;
    const int akc = (tid & 1) * 16;

    for (int k0 = 0; k0 < DD; k0 += 32) {
#pragma unroll
        for (int t = 0; t < 4; t++) {
            float4 v = *(const float4*)&A[(size_t)(i0 + arow) * DD + k0 + akc + t * 4];
            As[akc + t * 4 + 0][arow] = f2tf32f(v.x);
            As[akc + t * 4 + 1][arow] = f2tf32f(v.y);
            As[akc + t * 4 + 2][arow] = f2tf32f(v.z);
            As[akc + t * 4 + 3][arow] = f2tf32f(v.w);
        }
#pragma unroll
        for (int t = 0; t < 4; t++) {
            int f4id = tid + t * 256;
            int kk = f4id >> 5;
            int nc = (f4id & 31) * 4;
            float4 v = *(const float4*)&B[(size_t)(k0 + kk) * FF + j0 + nc];
            float4 w;
            w.x = f2tf32f(v.x); w.y = f2tf32f(v.y);
            w.z = f2tf32f(v.z); w.w = f2tf32f(v.w);
            *(float4*)&Bs[kk][nc] = w;
        }
        __syncthreads();
#pragma unroll
        for (int ks = 0; ks < 32; ks += 8) {
            unsigned af[2][4];
#pragma unroll
            for (int mt = 0; mt < 2; mt++) {
                int m0 = wm + mt * 16;
                af[mt][0] = __float_as_uint(As[ks + tig][m0 + g]);
                af[mt][1] = __float_as_uint(As[ks + tig][m0 + g + 8]);
                af[mt][2] = __float_as_uint(As[ks + tig + 4][m0 + g]);
                af[mt][3] = __float_as_uint(As[ks + tig + 4][m0 + g + 8]);
            }
            unsigned bf[8][2];
#pragma unroll
            for (int nt = 0; nt < 8; nt++) {
                int n0 = wn + nt * 8;
                bf[nt][0] = __float_as_uint(Bs[ks + tig][n0 + g]);
                bf[nt][1] = __float_as_uint(Bs[ks + tig + 4][n0 + g]);
            }
#pragma unroll
            for (int mt = 0; mt < 2; mt++)
#pragma unroll
                for (int nt = 0; nt < 8; nt++)
                    mma_tf32(acc[mt][nt], af[mt], bf[nt]);
        }
        __syncthreads();
    }
#pragma unroll
    for (int mt = 0; mt < 2; mt++) {
        int gi = i0 + wm + mt * 16 + g;
#pragma unroll
        for (int nt = 0; nt < 8; nt++) {
            int gj = j0 + wn + nt * 8 + tig * 2;
            float bx = bias[gj], by = bias[gj + 1];
            float2 v0, v1;
            v0.x = acc[mt][nt][0] + bx; v0.y = acc[mt][nt][1] + by;
            v1.x = acc[mt][nt][2] + bx; v1.y = acc[mt][nt][3] + by;
            *(float2*)&C[(size_t)gi * FF + gj] = v0;
            *(float2*)&C[(size_t)(gi + 8) * FF + gj] = v1;
        }
    }
}

// ============================================================
// Kernel 2: row softmax on g_w
// ============================================================
__global__ void softmax_rows() {
    const int row = blockIdx.x;
    const int tid = threadIdx.x;
    const int lane = tid & 31;
    const int wid = tid >> 5;
    float4* p = ((float4*)g_w) + (size_t)row * (EE / 4);
    float4 v = p[tid];
    __shared__ float red[8];
    __shared__ float bc;

    float m = fmaxf(fmaxf(v.x, v.y), fmaxf(v.z, v.w));
#pragma unroll
    for (int o = 16; o > 0; o >>= 1) m = fmaxf(m, __shfl_xor_sync(0xffffffffu, m, o));
    if (lane == 0) red[wid] = m;
    __syncthreads();
    if (tid == 0) {
        float t = red[0];
#pragma unroll
        for (int i = 1; i < 8; i++) t = fmaxf(t, red[i]);
        bc = t;
    }
    __syncthreads();
    m = bc;
    __syncthreads();
    v.x = expf(v.x - m); v.y = expf(v.y - m);
    v.z = expf(v.z - m); v.w = expf(v.w - m);
    float s = v.x + v.y + v.z + v.w;
#pragma unroll
    for (int o = 16; o > 0; o >>= 1) s += __shfl_xor_sync(0xffffffffu, s, o);
    if (lane == 0) red[wid] = s;
    __syncthreads();
    if (tid == 0) {
        float t = 0.f;
#pragma unroll
        for (int i = 0; i < 8; i++) t += red[i];
        bc = t;
    }
    __syncthreads();
    float inv = 1.f / bc;
    v.x *= inv; v.y *= inv; v.z *= inv; v.w *= inv;
    p[tid] = v;
}

// ============================================================
// Kernel 3: x -> fp16 (8 floats / thread)
// ============================================================
__global__ void cvt_x(const float* __restrict__ x) {
    const int idx = blockIdx.x * 256 + threadIdx.x;
    float4 v0 = ((const float4*)x)[idx * 2];
    float4 v1 = ((const float4*)x)[idx * 2 + 1];
    __half2 h[4];
    h[0] = __floats2half2_rn(v0.x, v0.y);
    h[1] = __floats2half2_rn(v0.z, v0.w);
    h[2] = __floats2half2_rn(v1.x, v1.y);
    h[3] = __floats2half2_rn(v1.z, v1.w);
    ((uint4*)g_xh)[idx] = *(uint4*)h;
}

// ============================================================
// Kernel 4: split-K W_eff partials + b_eff fold.
// grid (32 d-tiles, 18 e-chunks) = 576 CTAs = one wave @4 CTA/SM.
// DT=8 keeps regs ~60 so 4 CTAs/SM fit -> 32 warps covering DRAM latency.
// ============================================================
__global__ void __launch_bounds__(256, 4)
weff_partial(const float* __restrict__ eW, const float* __restrict__ eb) {
    const int tid = threadIdx.x;
    const int d0 = blockIdx.x * DT;
    const int es = blockIdx.y;
    const int e0 = (es * EE) / NCHUNK;
    const int e1 = ((es + 1) * EE) / NCHUNK;
    const bool doB = (blockIdx.x == 0);

    float4 acc[DT];
#pragma unroll
    for (int i = 0; i < DT; i++) acc[i] = make_float4(0.f, 0.f, 0.f, 0.f);
    float4 bacc = make_float4(0.f, 0.f, 0.f, 0.f);

    const float4* wp = ((const float4*)g_w) + tid;
    const float4* ep = ((const float4*)eW) + (size_t)d0 * (FF / 4) + tid;
    const float4* bp = ((const float4*)eb) + tid;

    for (int e = e0; e < e1; e++) {
        float4 wv = wp[(size_t)e * (FF / 4)];
        if (doB) {
            float4 bv = __ldcs(bp + (size_t)e * (FF / 4));
            bacc.x += wv.x * bv.x; bacc.y += wv.y * bv.y;
            bacc.z += wv.z * bv.z; bacc.w += wv.w * bv.w;
        }
        const float4* ee = ep + (size_t)e * DD * (FF / 4);
#pragma unroll
        for (int dd = 0; dd < DT; dd++) {
            float4 ev = __ldcs(ee + (size_t)dd * (FF / 4));
            acc[dd].x += wv.x * ev.x;
            acc[dd].y += wv.y * ev.y;
            acc[dd].z += wv.z * ev.z;
            acc[dd].w += wv.w * ev.w;
        }
    }
    float4* outp = ((float4*)g_part) + ((size_t)es * DD + d0) * (FF / 4) + tid;
#pragma unroll
    for (int dd = 0; dd < DT; dd++) outp[(size_t)dd * (FF / 4)] = acc[dd];
    if (doB) ((float4*)g_bpart)[(size_t)es * (FF / 4) + tid] = bacc;
}

// ============================================================
// Kernel 5: deterministic reduce over 18 chunks (9+9 halves,
// fixed order) -> emit W_eff^T fp16 [f][d] + beff.
// ============================================================
__global__ void reduce_parts() {
    __shared__ float4 sh[128];
    const int t = threadIdx.x;
    const int lane128 = t & 127;
    const int half_ = t >> 7;
    const int idx = blockIdx.x * 128 + lane128;

    const float4* src = ((const float4*)g_part) + (size_t)(half_ * 9) * P4 + idx;
    float4 s = make_float4(0.f, 0.f, 0.f, 0.f);
#pragma unroll
    for (int p = 0; p < 9; p++) {
        float4 v = src[(size_t)p * P4];
        s.x += v.x; s.y += v.y; s.z += v.z; s.w += v.w;
    }
    if (half_) sh[lane128] = s;
    __syncthreads();
    if (!half_) {
        float4 h = sh[lane128];
        float vals[4];
        vals[0] = s.x + h.x; vals[1] = s.y + h.y;
        vals[2] = s.z + h.z; vals[3] = s.w + h.w;
        const int d = idx >> 8;            // k index
        const int f = (idx & 255) * 4;     // n base
#pragma unroll
        for (int j = 0; j < 4; j++)
            g_wth[(size_t)(f + j) * DD + d] = __float2half_rn(vals[j]);
    }
    if (blockIdx.x == 0) {
        float4 b = make_float4(0.f, 0.f, 0.f, 0.f);
#pragma unroll
        for (int p = 0; p < NCHUNK; p++) {
            float4 v = ((const float4*)g_bpart)[(size_t)p * (FF / 4) + t];
            b.x += v.x; b.y += v.y; b.z += v.z; b.w += v.w;
        }
        ((float4*)g_beff)[t] = b;
    }
}

// ============================================================
// Kernel 6: final GEMM, fp16 HMMA m16n8k16, fp32 accumulate.
// CTA 128x128, 8 warps, warp tile 32x64, BK=64. (proven)
// ============================================================
__global__ void __launch_bounds__(256, 2)
final_hmma(float* __restrict__ out) {
    __shared__ __align__(16) __half As[128][72];
    __shared__ __align__(16) __half Bs[128][72];
    const int tid = threadIdx.x;
    const int wid = tid >> 5;
    const int lane = tid & 31;
    const int g = lane >> 2;
    const int tig = lane & 3;
    const int i0 = blockIdx.y * 128;
    const int j0 = blockIdx.x * 128;
    const int wm = (wid >> 1) * 32;
    const int wn = (wid & 1) * 64;

    float acc[2][8][4];
#pragma unroll
    for (int mt = 0; mt < 2; mt++)
#pragma unroll
        for (int nt = 0; nt < 8; nt++)
#pragma unroll
            for (int r = 0; r < 4; r++) acc[mt][nt][r] = 0.f;

    for (int kc = 0; kc < DD; kc += 64) {
#pragma unroll
        for (int t = 0; t < 4; t++) {
            int idx = tid + t * 256;
            int r = idx >> 3, c8 = idx & 7;
            *(uint4*)&As[r][c8 * 8] =
                *(const uint4*)(g_xh + (size_t)(i0 + r) * DD + kc + c8 * 8);
        }
#pragma unroll
        for (int t = 0; t < 4; t++) {
            int idx = tid + t * 256;
            int r = idx >> 3, c8 = idx & 7;
            *(uint4*)&Bs[r][c8 * 8] =
                *(const uint4*)(g_wth + (size_t)(j0 + r) * DD + kc + c8 * 8);
        }
        __syncthreads();

#pragma unroll
        for (int ks = 0; ks < 64; ks += 16) {
            unsigned af[2][4];
#pragma unroll
            for (int mt = 0; mt < 2; mt++) {
                int m0 = wm + mt * 16;
                af[mt][0] = *(const unsigned*)&As[m0 + g][ks + tig * 2];
                af[mt][1] = *(const unsigned*)&As[m0 + g + 8][ks + tig * 2];
                af[mt][2] = *(const unsigned*)&As[m0 + g][ks + tig * 2 + 8];
                af[mt][3] = *(const unsigned*)&As[m0 + g + 8][ks + tig * 2 + 8];
            }
            unsigned bf[8][2];
#pragma unroll
            for (int nt = 0; nt < 8; nt++) {
                int n0 = wn + nt * 8;
                bf[nt][0] = *(const unsigned*)&Bs[n0 + g][ks + tig * 2];
                bf[nt][1] = *(const unsigned*)&Bs[n0 + g][ks + tig * 2 + 8];
            }
#pragma unroll
            for (int mt = 0; mt < 2; mt++)
#pragma unroll
                for (int nt = 0; nt < 8; nt++)
                    mma_f16(acc[mt][nt], af[mt], bf[nt]);
        }
        __syncthreads();
    }

#pragma unroll
    for (int mt = 0; mt < 2; mt++) {
        int gi = i0 + wm + mt * 16 + g;
#pragma unroll
        for (int nt = 0; nt < 8; nt++) {
            int gj = j0 + wn + nt * 8 + tig * 2;
            float bx = g_beff[gj], by = g_beff[gj + 1];
            float2 v0, v1;
            v0.x = acc[mt][nt][0] + bx; v0.y = acc[mt][nt][1] + by;
            v1.x = acc[mt][nt][2] + bx; v1.y = acc[mt][nt][3] + by;
            *(float2*)&out[(size_t)gi * FF + gj] = v0;
            *(float2*)&out[(size_t)(gi + 8) * FF + gj] = v1;
        }
    }
}

// ============================================================
extern "C" void kernel_launch(void* const* d_in, const int* in_sizes, int n_in,
                              void* d_out, int out_size) {
    const float* x  = (const float*)d_in[0];   // (4096, 256)
    const float* gW = (const float*)d_in[1];   // (256, 1024)
    const float* gb = (const float*)d_in[2];   // (1024,)
    const float* eW = (const float*)d_in[3];   // (1024, 256, 1024)
    const float* eb = (const float*)d_in[4];   // (1024, 1024)
    float* out = (float*)d_out;                // (4096, 1024)

    cvt_x<<<NROWS * DD / 8 / 256, 256>>>(x);
    gate_tf32<<<dim3(FF / 128, EE / 128), 256>>>(x, gW, gb);
    softmax_rows<<<EE, 256>>>();
    weff_partial<<<dim3(DD / DT, NCHUNK), 256>>>(eW, eb);
    reduce_parts<<<P4 / 128, 256>>>();
    final_hmma<<<dim3(FF / 128, NROWS / 128), 256>>>(out);
}